// round 2
// baseline (speedup 1.0000x reference)
#include <cuda_runtime.h>
#include <math_constants.h>

#define BB 4
#define NN 4096
#define DD 256

// Scratch (device globals: allocation-free rule)
__device__ float g_Qt[(size_t)BB*DD*NN];   // (b, d, n)  16 MB
__device__ float g_Kt[(size_t)BB*DD*NN];   // (b, d, n)  16 MB
__device__ float g_V [(size_t)BB*NN*DD];   // (b, n, d)  16 MB
__device__ float g_S [(size_t)BB*NN*NN];   // (b, nq, nk) 268 MB

// ---------------------------------------------------------------------------
// Kernel 1: fused QKV projection.
//   A[m][k] = x[b][k][m]  (x is (B,D,N), so k-major rows are n-contiguous)
//   C = A @ W + bias
//   w==0 -> Qt (d-major), w==1 -> Kt (d-major), w==2 -> V (n,d row-major)
// ---------------------------------------------------------------------------
__global__ __launch_bounds__(256, 2) void proj_kernel(
    const float* __restrict__ x,
    const float* __restrict__ Wq, const float* __restrict__ bq,
    const float* __restrict__ Wk, const float* __restrict__ bk,
    const float* __restrict__ Wv, const float* __restrict__ bv)
{
    __shared__ float As[16][132];
    __shared__ float Bs[16][132];

    const int bz = blockIdx.z;
    const int b  = bz / 3;
    const int w  = bz % 3;
    const float* W    = (w == 0) ? Wq : ((w == 1) ? Wk : Wv);
    const float* bias = (w == 0) ? bq : ((w == 1) ? bk : bv);

    const int m0 = blockIdx.x * 128;   // n-range
    const int d0 = blockIdx.y * 128;   // output-d range
    const int tid = threadIdx.x;
    const int tx = tid & 15, ty = tid >> 4;

    const float* Abase = x + (size_t)b * DD * NN;  // A[k][m] = Abase[k*NN + m]

    float acc[8][8] = {};
    float4 pa[2], pb[2];

    // prefetch chunk 0
    #pragma unroll
    for (int u = 0; u < 2; ++u) {
        int idx = tid + u * 256;
        int kl = idx >> 5, m4 = (idx & 31) << 2;
        pa[u] = *(const float4*)(Abase + (size_t)kl * NN + m0 + m4);
        pb[u] = *(const float4*)(W     + (size_t)kl * DD + d0 + m4);
    }

    for (int kc = 0; kc < DD; kc += 16) {
        #pragma unroll
        for (int u = 0; u < 2; ++u) {
            int idx = tid + u * 256;
            int kl = idx >> 5, m4 = (idx & 31) << 2;
            *(float4*)&As[kl][m4] = pa[u];
            *(float4*)&Bs[kl][m4] = pb[u];
        }
        __syncthreads();
        if (kc + 16 < DD) {
            int kn = kc + 16;
            #pragma unroll
            for (int u = 0; u < 2; ++u) {
                int idx = tid + u * 256;
                int kl = idx >> 5, m4 = (idx & 31) << 2;
                pa[u] = *(const float4*)(Abase + (size_t)(kn + kl) * NN + m0 + m4);
                pb[u] = *(const float4*)(W     + (size_t)(kn + kl) * DD + d0 + m4);
            }
        }
        #pragma unroll
        for (int kk = 0; kk < 16; ++kk) {
            float a[8], bv2[8];
            *(float4*)&a[0]   = *(float4*)&As[kk][ty * 8];
            *(float4*)&a[4]   = *(float4*)&As[kk][ty * 8 + 4];
            *(float4*)&bv2[0] = *(float4*)&Bs[kk][tx * 8];
            *(float4*)&bv2[4] = *(float4*)&Bs[kk][tx * 8 + 4];
            #pragma unroll
            for (int i = 0; i < 8; ++i)
                #pragma unroll
                for (int j = 0; j < 8; ++j)
                    acc[i][j] += a[i] * bv2[j];
        }
        __syncthreads();
    }

    if (w < 2) {
        // transposed epilogue: Out[d][n]
        float* Out = ((w == 0) ? g_Qt : g_Kt) + (size_t)b * DD * NN;
        #pragma unroll
        for (int j = 0; j < 8; ++j) {
            int d = d0 + tx * 8 + j;
            float bbv = bias[d];
            float4 v0 = make_float4(acc[0][j] + bbv, acc[1][j] + bbv,
                                    acc[2][j] + bbv, acc[3][j] + bbv);
            float4 v1 = make_float4(acc[4][j] + bbv, acc[5][j] + bbv,
                                    acc[6][j] + bbv, acc[7][j] + bbv);
            *(float4*)(Out + (size_t)d * NN + m0 + ty * 8)     = v0;
            *(float4*)(Out + (size_t)d * NN + m0 + ty * 8 + 4) = v1;
        }
    } else {
        // row-major epilogue: V[n][d]
        float* Out = g_V + (size_t)b * NN * DD;
        #pragma unroll
        for (int i = 0; i < 8; ++i) {
            int n = m0 + ty * 8 + i;
            int d = d0 + tx * 8;
            float4 v0 = make_float4(acc[i][0] + bias[d + 0], acc[i][1] + bias[d + 1],
                                    acc[i][2] + bias[d + 2], acc[i][3] + bias[d + 3]);
            float4 v1 = make_float4(acc[i][4] + bias[d + 4], acc[i][5] + bias[d + 5],
                                    acc[i][6] + bias[d + 6], acc[i][7] + bias[d + 7]);
            *(float4*)(Out + (size_t)n * DD + d)     = v0;
            *(float4*)(Out + (size_t)n * DD + d + 4) = v1;
        }
    }
}

// ---------------------------------------------------------------------------
// Kernel 2: S[b][m][j] = sum_d Qt[b][d][m] * Kt[b][d][j]
// Both operands d-major -> straight coalesced loads into [k][128] smem tiles.
// ---------------------------------------------------------------------------
__global__ __launch_bounds__(256, 2) void qk_kernel()
{
    __shared__ float As[16][132];
    __shared__ float Bs[16][132];

    const int b  = blockIdx.z;
    const int m0 = blockIdx.y * 128;
    const int j0 = blockIdx.x * 128;
    const int tid = threadIdx.x;
    const int tx = tid & 15, ty = tid >> 4;

    const float* Qb = g_Qt + (size_t)b * DD * NN;
    const float* Kb = g_Kt + (size_t)b * DD * NN;

    float acc[8][8] = {};
    float4 pa[2], pb[2];

    #pragma unroll
    for (int u = 0; u < 2; ++u) {
        int idx = tid + u * 256;
        int kl = idx >> 5, m4 = (idx & 31) << 2;
        pa[u] = *(const float4*)(Qb + (size_t)kl * NN + m0 + m4);
        pb[u] = *(const float4*)(Kb + (size_t)kl * NN + j0 + m4);
    }

    for (int kc = 0; kc < DD; kc += 16) {
        #pragma unroll
        for (int u = 0; u < 2; ++u) {
            int idx = tid + u * 256;
            int kl = idx >> 5, m4 = (idx & 31) << 2;
            *(float4*)&As[kl][m4] = pa[u];
            *(float4*)&Bs[kl][m4] = pb[u];
        }
        __syncthreads();
        if (kc + 16 < DD) {
            int kn = kc + 16;
            #pragma unroll
            for (int u = 0; u < 2; ++u) {
                int idx = tid + u * 256;
                int kl = idx >> 5, m4 = (idx & 31) << 2;
                pa[u] = *(const float4*)(Qb + (size_t)(kn + kl) * NN + m0 + m4);
                pb[u] = *(const float4*)(Kb + (size_t)(kn + kl) * NN + j0 + m4);
            }
        }
        #pragma unroll
        for (int kk = 0; kk < 16; ++kk) {
            float a[8], bv2[8];
            *(float4*)&a[0]   = *(float4*)&As[kk][ty * 8];
            *(float4*)&a[4]   = *(float4*)&As[kk][ty * 8 + 4];
            *(float4*)&bv2[0] = *(float4*)&Bs[kk][tx * 8];
            *(float4*)&bv2[4] = *(float4*)&Bs[kk][tx * 8 + 4];
            #pragma unroll
            for (int i = 0; i < 8; ++i)
                #pragma unroll
                for (int j = 0; j < 8; ++j)
                    acc[i][j] += a[i] * bv2[j];
        }
        __syncthreads();
    }

    #pragma unroll
    for (int i = 0; i < 8; ++i) {
        float* Srow = g_S + ((size_t)b * NN + m0 + ty * 8 + i) * NN + j0 + tx * 8;
        *(float4*)(Srow)     = make_float4(acc[i][0], acc[i][1], acc[i][2], acc[i][3]);
        *(float4*)(Srow + 4) = make_float4(acc[i][4], acc[i][5], acc[i][6], acc[i][7]);
    }
}

// ---------------------------------------------------------------------------
// Kernel 3: row softmax over g_S, in place. One block per row (4096 floats).
// ---------------------------------------------------------------------------
__inline__ __device__ float warpMax(float v) {
    #pragma unroll
    for (int o = 16; o; o >>= 1) v = fmaxf(v, __shfl_xor_sync(0xffffffffu, v, o));
    return v;
}
__inline__ __device__ float warpSum(float v) {
    #pragma unroll
    for (int o = 16; o; o >>= 1) v += __shfl_xor_sync(0xffffffffu, v, o);
    return v;
}

__global__ __launch_bounds__(256) void softmax_kernel()
{
    __shared__ float red[8];
    const size_t row = blockIdx.x;
    float* p = g_S + row * (size_t)NN;
    const int tid = threadIdx.x;
    const int lane = tid & 31, wid = tid >> 5;

    float4 v[4];
    float m = -CUDART_INF_F;
    #pragma unroll
    for (int u = 0; u < 4; ++u) {
        v[u] = *(float4*)(p + (size_t)(tid + u * 256) * 4);
        m = fmaxf(m, fmaxf(fmaxf(v[u].x, v[u].y), fmaxf(v[u].z, v[u].w)));
    }
    m = warpMax(m);
    if (lane == 0) red[wid] = m;
    __syncthreads();
    float bm = red[0];
    #pragma unroll
    for (int i = 1; i < 8; ++i) bm = fmaxf(bm, red[i]);
    __syncthreads();

    float s = 0.f;
    #pragma unroll
    for (int u = 0; u < 4; ++u) {
        v[u].x = __expf(v[u].x - bm);
        v[u].y = __expf(v[u].y - bm);
        v[u].z = __expf(v[u].z - bm);
        v[u].w = __expf(v[u].w - bm);
        s += v[u].x + v[u].y + v[u].z + v[u].w;
    }
    s = warpSum(s);
    if (lane == 0) red[wid] = s;
    __syncthreads();
    float tot = 0.f;
    #pragma unroll
    for (int i = 0; i < 8; ++i) tot += red[i];
    float inv = 1.0f / tot;

    #pragma unroll
    for (int u = 0; u < 4; ++u) {
        v[u].x *= inv; v[u].y *= inv; v[u].z *= inv; v[u].w *= inv;
        *(float4*)(p + (size_t)(tid + u * 256) * 4) = v[u];
    }
}

// ---------------------------------------------------------------------------
// Kernel 4: O = P @ V.  P = g_S (m x 4096), V (4096 x 256).
// Output written directly to d_out in (B, D, N) layout (transposed epilogue).
// ---------------------------------------------------------------------------
__global__ __launch_bounds__(256, 2) void av_kernel(float* __restrict__ out)
{
    __shared__ float As[16][132];
    __shared__ float Bs[16][132];

    const int b  = blockIdx.z;
    const int m0 = blockIdx.y * 128;   // query rows
    const int d0 = blockIdx.x * 128;   // output d
    const int tid = threadIdx.x;
    const int tx = tid & 15, ty = tid >> 4;

    const float* Pb = g_S + (size_t)b * NN * NN;  // [m][key]
    const float* Vb = g_V + (size_t)b * NN * DD;  // [key][d]

    float acc[8][8] = {};
    float4 pa[2], pb[2];

    // prefetch chunk 0
    #pragma unroll
    for (int u = 0; u < 2; ++u) {
        int idxA = tid + u * 256;
        int ml = idxA >> 2, c4 = (idxA & 3) << 2;
        pa[u] = *(const float4*)(Pb + (size_t)(m0 + ml) * NN + c4);
        int kl = idxA >> 5, d4 = (idxA & 31) << 2;
        pb[u] = *(const float4*)(Vb + (size_t)kl * DD + d0 + d4);
    }

    for (int kc = 0; kc < NN; kc += 16) {
        #pragma unroll
        for (int u = 0; u < 2; ++u) {
            int idxA = tid + u * 256;
            int ml = idxA >> 2, c4 = (idxA & 3) << 2;
            As[c4 + 0][ml] = pa[u].x;   // transpose-scatter P tile to [k][m]
            As[c4 + 1][ml] = pa[u].y;
            As[c4 + 2][ml] = pa[u].z;
            As[c4 + 3][ml] = pa[u].w;
            int kl = idxA >> 5, d4 = (idxA & 31) << 2;
            *(float4*)&Bs[kl][d4] = pb[u];
        }
        __syncthreads();
        if (kc + 16 < NN) {
            int kn = kc + 16;
            #pragma unroll
            for (int u = 0; u < 2; ++u) {
                int idxA = tid + u * 256;
                int ml = idxA >> 2, c4 = (idxA & 3) << 2;
                pa[u] = *(const float4*)(Pb + (size_t)(m0 + ml) * NN + kn + c4);
                int kl = idxA >> 5, d4 = (idxA & 31) << 2;
                pb[u] = *(const float4*)(Vb + (size_t)(kn + kl) * DD + d0 + d4);
            }
        }
        #pragma unroll
        for (int kk = 0; kk < 16; ++kk) {
            float a[8], bv2[8];
            *(float4*)&a[0]   = *(float4*)&As[kk][ty * 8];
            *(float4*)&a[4]   = *(float4*)&As[kk][ty * 8 + 4];
            *(float4*)&bv2[0] = *(float4*)&Bs[kk][tx * 8];
            *(float4*)&bv2[4] = *(float4*)&Bs[kk][tx * 8 + 4];
            #pragma unroll
            for (int i = 0; i < 8; ++i)
                #pragma unroll
                for (int j = 0; j < 8; ++j)
                    acc[i][j] += a[i] * bv2[j];
        }
        __syncthreads();
    }

    // output (B, D, N): out[b][d][n]
    float* Ob = out + (size_t)b * DD * NN;
    #pragma unroll
    for (int j = 0; j < 8; ++j) {
        int d = d0 + tx * 8 + j;
        float4 v0 = make_float4(acc[0][j], acc[1][j], acc[2][j], acc[3][j]);
        float4 v1 = make_float4(acc[4][j], acc[5][j], acc[6][j], acc[7][j]);
        *(float4*)(Ob + (size_t)d * NN + m0 + ty * 8)     = v0;
        *(float4*)(Ob + (size_t)d * NN + m0 + ty * 8 + 4) = v1;
    }
}

// ---------------------------------------------------------------------------
extern "C" void kernel_launch(void* const* d_in, const int* in_sizes, int n_in,
                              void* d_out, int out_size)
{
    const float* x  = (const float*)d_in[0];
    const float* Wq = (const float*)d_in[1];
    const float* bq = (const float*)d_in[2];
    const float* Wk = (const float*)d_in[3];
    const float* bk = (const float*)d_in[4];
    const float* Wv = (const float*)d_in[5];
    const float* bv = (const float*)d_in[6];
    float* out = (float*)d_out;

    proj_kernel<<<dim3(NN / 128, DD / 128, BB * 3), 256>>>(x, Wq, bq, Wk, bk, Wv, bv);
    qk_kernel<<<dim3(NN / 128, NN / 128, BB), 256>>>();
    softmax_kernel<<<BB * NN, 256>>>();
    av_kernel<<<dim3(DD / 128, NN / 128, BB), 256>>>(out);
}

// round 4
// speedup vs baseline: 2.1376x; 2.1376x over previous
#include <cuda_runtime.h>
#include <cuda_fp16.h>
#include <math_constants.h>
#include <cstdint>

#define BB 4
#define NN 4096
#define DD 256

// ---------------- device scratch (allocation-free rule) ----------------
__device__ __align__(128) __half g_Qhi[(size_t)BB*NN*DD];   // [b][n][d]
__device__ __align__(128) __half g_Qlo[(size_t)BB*NN*DD];
__device__ __align__(128) __half g_Khi[(size_t)BB*NN*DD];   // [b][n][d]
__device__ __align__(128) __half g_Klo[(size_t)BB*NN*DD];
__device__ __align__(128) __half g_Vthi[(size_t)BB*DD*NN];  // [b][d][key]
__device__ __align__(128) __half g_Vtlo[(size_t)BB*DD*NN];
__device__ __align__(128) __half g_Phi[(size_t)BB*NN*NN];   // [b][q][key]
__device__ __align__(128) __half g_Plo[(size_t)BB*NN*NN];
__device__ __align__(128) float  g_S [(size_t)BB*NN*NN];    // [b][q][key]

// ---------------- helpers ----------------
__device__ __forceinline__ uint32_t smem_u32(const void* p) {
    uint32_t a;
    asm("{ .reg .u64 t; cvta.to.shared.u64 t, %1; cvt.u32.u64 %0, t; }" : "=r"(a) : "l"(p));
    return a;
}

#define LDM4(r, addr) asm volatile( \
    "ldmatrix.sync.aligned.m8n8.x4.shared.b16 {%0,%1,%2,%3}, [%4];" \
    : "=r"((r)[0]), "=r"((r)[1]), "=r"((r)[2]), "=r"((r)[3]) : "r"(addr))

#define MMA16816(c, a, b0, b1) asm volatile( \
    "mma.sync.aligned.m16n8k16.row.col.f32.f16.f16.f32 " \
    "{%0,%1,%2,%3}, {%4,%5,%6,%7}, {%8,%9}, {%0,%1,%2,%3};" \
    : "+f"((c)[0]), "+f"((c)[1]), "+f"((c)[2]), "+f"((c)[3]) \
    : "r"((a)[0]), "r"((a)[1]), "r"((a)[2]), "r"((a)[3]), "r"(b0), "r"(b1))

#define CP16(so, ga) asm volatile("cp.async.cg.shared.global [%0], [%1], 16;" \
    :: "r"(so), "l"(ga) : "memory")
#define CP_COMMIT() asm volatile("cp.async.commit_group;" ::: "memory")
#define CP_WAIT1()  asm volatile("cp.async.wait_group 1;" ::: "memory")

// 64B-pitch tile with xor swizzle on 16B chunks: conflict-free for ldmatrix + cp.async
__device__ __forceinline__ uint32_t swz(uint32_t tile, int row, int chunk) {
    return tile + (uint32_t)row * 64u + ((uint32_t)((chunk ^ ((row >> 1) & 3)) & 3) << 4);
}

#define TILE_B   8192u    // 128 rows x 64B
#define STAGE_B  32768u   // Ahi, Alo, Bhi, Blo
#define SMEM_SZ  (3 * 32768)

// ---------------------------------------------------------------------------
// Unified split-fp16 HMMA GEMM (TN): C[128,128](fp32) += A(128,K) . B(128,K)^T
// where A ~ Ahi+Alo, B ~ Bhi+Blo; computes hh + hl + lh.
// mode 0: QK -> g_S.   mode 1: AV -> out (B,D,N).
// ---------------------------------------------------------------------------
__global__ __launch_bounds__(256, 1) void hmma_kernel(int mode, float* __restrict__ outp)
{
    extern __shared__ __align__(128) char sm[];
    const int tid  = threadIdx.x;
    const int lane = tid & 31, wid = tid >> 5;
    const int wm = wid & 3, wn = wid >> 2;
    const int bx = blockIdx.x, by = blockIdx.y, bz = blockIdx.z;

    const __half *Ahi, *Alo, *Bhi, *Blo;
    float* C;
    size_t lda, ldb;
    int nchunks;
    if (mode == 0) {
        size_t ab = ((size_t)bz * NN + (size_t)by * 128) * DD;
        size_t bb = ((size_t)bz * NN + (size_t)bx * 128) * DD;
        Ahi = g_Qhi + ab;  Alo = g_Qlo + ab;
        Bhi = g_Khi + bb;  Blo = g_Klo + bb;
        C = g_S + (size_t)bz * NN * NN + (size_t)by * 128 * NN + (size_t)bx * 128;
        lda = DD; ldb = DD; nchunks = DD / 32;       // 8
    } else {
        size_t ab = (size_t)bz * DD * NN + (size_t)by * 128 * NN;
        size_t bb = (size_t)bz * NN * NN + (size_t)bx * 128 * NN;
        Ahi = g_Vthi + ab; Alo = g_Vtlo + ab;
        Bhi = g_Phi  + bb; Blo = g_Plo  + bb;
        C = outp + (size_t)bz * DD * NN + (size_t)by * 128 * NN + (size_t)bx * 128;
        lda = NN; ldb = NN; nchunks = NN / 32;       // 128
    }

    const uint32_t sbase = smem_u32(sm);

    auto load_stage = [&](int s, int ch) {
        uint32_t st = sbase + (uint32_t)s * STAGE_B;
        size_t k0 = (size_t)ch * 32;
        const __half* gp[4] = { Ahi + k0, Alo + k0, Bhi + k0, Blo + k0 };
        #pragma unroll
        for (int t2 = 0; t2 < 4; ++t2) {
            uint32_t tb = st + (uint32_t)t2 * TILE_B;
            size_t ld = (t2 < 2) ? lda : ldb;
            const __half* g = gp[t2];
            #pragma unroll
            for (int i = 0; i < 2; ++i) {
                int id = tid + i * 256;
                int row = id >> 2, c = id & 3;
                CP16(swz(tb, row, c), g + (size_t)row * ld + c * 8);
            }
        }
    };

    float acc[2][8][4] = {};

    auto compute = [&](int s) {
        uint32_t st  = sbase + (uint32_t)s * STAGE_B;
        uint32_t tAh = st, tAl = st + TILE_B, tBh = st + 2*TILE_B, tBl = st + 3*TILE_B;
        #pragma unroll
        for (int ks = 0; ks < 2; ++ks) {
            uint32_t ah[2][4], al[2][4], bh[4][4], bl[4][4];
            const int arow = wm * 32 + (lane & 15);
            const int achk = ks * 2 + (lane >> 4);
            #pragma unroll
            for (int mt = 0; mt < 2; ++mt) {
                LDM4(ah[mt], swz(tAh, arow + mt * 16, achk));
                LDM4(al[mt], swz(tAl, arow + mt * 16, achk));
            }
            const int brow = wn * 64 + ((lane >> 4) << 3) + (lane & 7);
            const int bchk = ks * 2 + ((lane >> 3) & 1);
            #pragma unroll
            for (int nt = 0; nt < 4; ++nt) {
                LDM4(bh[nt], swz(tBh, brow + nt * 16, bchk));
                LDM4(bl[nt], swz(tBl, brow + nt * 16, bchk));
            }
            #pragma unroll
            for (int mt = 0; mt < 2; ++mt)
                #pragma unroll
                for (int n8 = 0; n8 < 8; ++n8) {
                    const int g = n8 >> 1, h = (n8 & 1) * 2;
                    MMA16816(acc[mt][n8], ah[mt], bh[g][h], bh[g][h+1]);  // hi*hi
                    MMA16816(acc[mt][n8], ah[mt], bl[g][h], bl[g][h+1]);  // hi*lo
                    MMA16816(acc[mt][n8], al[mt], bh[g][h], bh[g][h+1]);  // lo*hi
                }
        }
    };

    load_stage(0, 0); CP_COMMIT();
    load_stage(1, 1); CP_COMMIT();

    for (int ch = 0; ch < nchunks; ++ch) {
        CP_WAIT1();
        __syncthreads();
        if (ch + 2 < nchunks) load_stage((ch + 2) % 3, ch + 2);
        CP_COMMIT();
        compute(ch % 3);
        __syncthreads();
    }

    // epilogue: fp32, 32B-coalesced segments
    const int r0 = wm * 32 + (lane >> 2);
    const int c0 = wn * 64 + (lane & 3) * 2;
    #pragma unroll
    for (int mt = 0; mt < 2; ++mt)
        #pragma unroll
        for (int n8 = 0; n8 < 8; ++n8) {
            float* p = C + (size_t)(r0 + mt * 16) * NN + c0 + n8 * 8;
            *(float2*)p            = make_float2(acc[mt][n8][0], acc[mt][n8][1]);
            *(float2*)(p + 8 * NN) = make_float2(acc[mt][n8][2], acc[mt][n8][3]);
        }
}

// ---------------------------------------------------------------------------
__device__ __forceinline__ void split8h(const float* v, uint4& uh, uint4& ul) {
    __half2 h[4], l[4];
    #pragma unroll
    for (int j = 0; j < 4; ++j) {
        float a = v[2*j], b = v[2*j+1];
        __half ha = __float2half_rn(a), hb = __float2half_rn(b);
        __half la = __float2half_rn(a - __half2float(ha));
        __half lb = __float2half_rn(b - __half2float(hb));
        h[j] = __halves2half2(ha, hb);
        l[j] = __halves2half2(la, lb);
    }
    uh = *(uint4*)h; ul = *(uint4*)l;
}

// Kernel 1: fused QKV projection (SIMT fp32), fp16 hi/lo epilogues.
__global__ __launch_bounds__(256, 2) void proj_kernel(
    const float* __restrict__ x,
    const float* __restrict__ Wq, const float* __restrict__ bq,
    const float* __restrict__ Wk, const float* __restrict__ bk,
    const float* __restrict__ Wv, const float* __restrict__ bv)
{
    __shared__ float As[16][132];
    __shared__ float Bs[16][132];

    const int bz = blockIdx.z;
    const int b  = bz / 3;
    const int w  = bz % 3;
    const float* W    = (w == 0) ? Wq : ((w == 1) ? Wk : Wv);
    const float* bias = (w == 0) ? bq : ((w == 1) ? bk : bv);

    const int m0 = blockIdx.x * 128;
    const int d0 = blockIdx.y * 128;
    const int tid = threadIdx.x;
    const int tx = tid & 15, ty = tid >> 4;
    const float* Abase = x + (size_t)b * DD * NN;

    float acc[8][8] = {};
    float4 pa[2], pb[2];
    #pragma unroll
    for (int u = 0; u < 2; ++u) {
        int idx = tid + u * 256;
        int kl = idx >> 5, m4 = (idx & 31) << 2;
        pa[u] = *(const float4*)(Abase + (size_t)kl * NN + m0 + m4);
        pb[u] = *(const float4*)(W     + (size_t)kl * DD + d0 + m4);
    }
    for (int kc = 0; kc < DD; kc += 16) {
        #pragma unroll
        for (int u = 0; u < 2; ++u) {
            int idx = tid + u * 256;
            int kl = idx >> 5, m4 = (idx & 31) << 2;
            *(float4*)&As[kl][m4] = pa[u];
            *(float4*)&Bs[kl][m4] = pb[u];
        }
        __syncthreads();
        if (kc + 16 < DD) {
            int kn = kc + 16;
            #pragma unroll
            for (int u = 0; u < 2; ++u) {
                int idx = tid + u * 256;
                int kl = idx >> 5, m4 = (idx & 31) << 2;
                pa[u] = *(const float4*)(Abase + (size_t)(kn + kl) * NN + m0 + m4);
                pb[u] = *(const float4*)(W     + (size_t)(kn + kl) * DD + d0 + m4);
            }
        }
        #pragma unroll
        for (int kk = 0; kk < 16; ++kk) {
            float a[8], bb[8];
            *(float4*)&a[0]  = *(float4*)&As[kk][ty * 8];
            *(float4*)&a[4]  = *(float4*)&As[kk][ty * 8 + 4];
            *(float4*)&bb[0] = *(float4*)&Bs[kk][tx * 8];
            *(float4*)&bb[4] = *(float4*)&Bs[kk][tx * 8 + 4];
            #pragma unroll
            for (int i = 0; i < 8; ++i)
                #pragma unroll
                for (int j = 0; j < 8; ++j)
                    acc[i][j] += a[i] * bb[j];
        }
        __syncthreads();
    }

    if (w < 2) {  // Q/K row-major [n][d]
        __half* Oh = ((w == 0) ? g_Qhi : g_Khi) + (size_t)b * NN * DD;
        __half* Ol = ((w == 0) ? g_Qlo : g_Klo) + (size_t)b * NN * DD;
        #pragma unroll
        for (int i = 0; i < 8; ++i) {
            int n = m0 + ty * 8 + i, d = d0 + tx * 8;
            float v[8];
            #pragma unroll
            for (int j = 0; j < 8; ++j) v[j] = acc[i][j] + bias[d + j];
            uint4 uh, ul; split8h(v, uh, ul);
            *(uint4*)(Oh + (size_t)n * DD + d) = uh;
            *(uint4*)(Ol + (size_t)n * DD + d) = ul;
        }
    } else {      // V transposed [d][n]
        __half* Oh = g_Vthi + (size_t)b * DD * NN;
        __half* Ol = g_Vtlo + (size_t)b * DD * NN;
        #pragma unroll
        for (int j = 0; j < 8; ++j) {
            int d = d0 + tx * 8 + j;
            float bb = bias[d];
            float v[8];
            #pragma unroll
            for (int i = 0; i < 8; ++i) v[i] = acc[i][j] + bb;
            uint4 uh, ul; split8h(v, uh, ul);
            *(uint4*)(Oh + (size_t)d * NN + m0 + ty * 8) = uh;
            *(uint4*)(Ol + (size_t)d * NN + m0 + ty * 8) = ul;
        }
    }
}

// Kernel 3: row softmax, fp32 S in, fp16 hi/lo P out.
__inline__ __device__ float warpMax(float v) {
    #pragma unroll
    for (int o = 16; o; o >>= 1) v = fmaxf(v, __shfl_xor_sync(0xffffffffu, v, o));
    return v;
}
__inline__ __device__ float warpSum(float v) {
    #pragma unroll
    for (int o = 16; o; o >>= 1) v += __shfl_xor_sync(0xffffffffu, v, o);
    return v;
}

__global__ __launch_bounds__(256) void softmax_kernel()
{
    __shared__ float red[8];
    const size_t row = blockIdx.x;
    const float* p = g_S + row * (size_t)NN;
    __half* ph = g_Phi + row * (size_t)NN;
    __half* pl = g_Plo + row * (size_t)NN;
    const int tid = threadIdx.x;
    const int lane = tid & 31, wid = tid >> 5;

    float4 v[4];
    float m = -CUDART_INF_F;
    #pragma unroll
    for (int u = 0; u < 4; ++u) {
        v[u] = *(const float4*)(p + (size_t)(tid + u * 256) * 4);
        m = fmaxf(m, fmaxf(fmaxf(v[u].x, v[u].y), fmaxf(v[u].z, v[u].w)));
    }
    m = warpMax(m);
    if (lane == 0) red[wid] = m;
    __syncthreads();
    float bm = red[0];
    #pragma unroll
    for (int i = 1; i < 8; ++i) bm = fmaxf(bm, red[i]);
    __syncthreads();

    float s = 0.f;
    #pragma unroll
    for (int u = 0; u < 4; ++u) {
        v[u].x = __expf(v[u].x - bm); v[u].y = __expf(v[u].y - bm);
        v[u].z = __expf(v[u].z - bm); v[u].w = __expf(v[u].w - bm);
        s += v[u].x + v[u].y + v[u].z + v[u].w;
    }
    s = warpSum(s);
    if (lane == 0) red[wid] = s;
    __syncthreads();
    float tot = 0.f;
    #pragma unroll
    for (int i = 0; i < 8; ++i) tot += red[i];
    float inv = 1.0f / tot;

    #pragma unroll
    for (int u = 0; u < 4; ++u) {
        size_t idx = (size_t)(tid + u * 256) * 4;
        float vv[4] = { v[u].x * inv, v[u].y * inv, v[u].z * inv, v[u].w * inv };
        __half h[4]; float lo[4];
        #pragma unroll
        for (int j = 0; j < 4; ++j) {
            h[j] = __float2half_rn(vv[j]);
            lo[j] = vv[j] - __half2float(h[j]);
        }
        *(__half2*)(ph + idx)     = __halves2half2(h[0], h[1]);
        *(__half2*)(ph + idx + 2) = __halves2half2(h[2], h[3]);
        *(__half2*)(pl + idx)     = __halves2half2(__float2half_rn(lo[0]), __float2half_rn(lo[1]));
        *(__half2*)(pl + idx + 2) = __halves2half2(__float2half_rn(lo[2]), __float2half_rn(lo[3]));
    }
}

// ---------------------------------------------------------------------------
extern "C" void kernel_launch(void* const* d_in, const int* in_sizes, int n_in,
                              void* d_out, int out_size)
{
    const float* x  = (const float*)d_in[0];
    const float* Wq = (const float*)d_in[1];
    const float* bq = (const float*)d_in[2];
    const float* Wk = (const float*)d_in[3];
    const float* bk = (const float*)d_in[4];
    const float* Wv = (const float*)d_in[5];
    const float* bv = (const float*)d_in[6];
    float* out = (float*)d_out;

    static bool attr_set = false;
    if (!attr_set) {
        cudaFuncSetAttribute(hmma_kernel, cudaFuncAttributeMaxDynamicSharedMemorySize, SMEM_SZ);
        attr_set = true;
    }

    proj_kernel<<<dim3(NN / 128, DD / 128, BB * 3), 256>>>(x, Wq, bq, Wk, bk, Wv, bv);
    hmma_kernel<<<dim3(NN / 128, NN / 128, BB), 256, SMEM_SZ>>>(0, nullptr);  // QK -> S
    softmax_kernel<<<BB * NN, 256>>>();
    hmma_kernel<<<dim3(NN / 128, DD / 128, BB), 256, SMEM_SZ>>>(1, out);      // AV -> out
}